// round 17
// baseline (speedup 1.0000x reference)
#include <cuda_runtime.h>
#include <cuda_fp16.h>
#include <math.h>
#include <stdint.h>

#define HID 128
#define BM  128
#define THREADS 512
#define NPB 32
#define N_NODES_MAX 100000

__device__ __half g_hsrc[N_NODES_MAX * HID];   // node_emb @ W1[0:128]
__device__ __half g_htgt[N_NODES_MAX * HID];   // node_emb @ W1[128:256]
__device__ __half g_w2h[4 * 4096];             // W2 chunks, uint4-paired frags
__device__ float  g_wx[2][16 * 128];
__device__ float  g_wp[2][3 * 128];
__device__ float  g_cb[2][128];

// fp16x2 silu: 0.5z(1+tanh(z/2)) — 1 MUFU per 2 values
__device__ __forceinline__ __half2 h2_silu(__half2 z) {
    __half2 hz = __hmul2(z, __float2half2_rn(0.5f));
    uint32_t th, hzin = *(uint32_t*)&hz;
    asm("tanh.approx.f16x2 %0, %1;" : "=r"(th) : "r"(hzin));
    return __hfma2(hz, *(__half2*)&th, hz);
}
__device__ __forceinline__ void mma16(float4& d, uint32_t a0, uint32_t a1,
                                      uint32_t a2, uint32_t a3,
                                      uint32_t b0, uint32_t b1) {
    asm volatile(
        "mma.sync.aligned.m16n8k16.row.col.f32.f16.f16.f32 "
        "{%0,%1,%2,%3},{%4,%5,%6,%7},{%8,%9},{%0,%1,%2,%3};"
        : "+f"(d.x), "+f"(d.y), "+f"(d.z), "+f"(d.w)
        : "r"(a0), "r"(a1), "r"(a2), "r"(a3), "r"(b0), "r"(b1));
}
__device__ __forceinline__ void ldm4(uint32_t& a0, uint32_t& a1,
                                     uint32_t& a2, uint32_t& a3, uint32_t addr) {
    asm volatile("ldmatrix.sync.aligned.m8n8.x4.shared.b16 {%0,%1,%2,%3},[%4];"
                 : "=r"(a0), "=r"(a1), "=r"(a2), "=r"(a3) : "r"(addr));
}
// swizzled 16B-chunk position within a 256B row (stays inside its 128B half)
__device__ __forceinline__ int sw_pos(int row, int cc) {
    return (cc & 8) + ((cc & 7) ^ (row & 7));
}

// ------------- Kernel 1: merged weight prep (8-way k-split, 1024 thr) -------
__global__ void __launch_bounds__(1024)
prep_all(const float* __restrict__ Wa, const float* __restrict__ ba,
         const float* __restrict__ Wp, const float* __restrict__ bp,
         const float* __restrict__ W1, const float* __restrict__ W2) {
    extern __shared__ float red[];   // [8][20][128] = 80 KB (blocks 0-1 only)
    if (blockIdx.x < 2) {
        __shared__ float swa[16 * 128];
        __shared__ float swp[3 * 128];
        __shared__ float sb[128];
        int p = blockIdx.x;
        int tid = threadIdx.x;
        int j = tid & 127;
        int kg = tid >> 7;          // 0..7
        for (int i = tid; i < 16 * 128; i += 1024) swa[i] = Wa[i];
        for (int i = tid; i < 3 * 128; i += 1024) swp[i] = Wp[i];
        if (tid < 128) sb[tid] = ba[tid] + bp[tid];
        __syncthreads();

        float ax[16];
#pragma unroll
        for (int i = 0; i < 16; i++) ax[i] = 0.f;
        float ap[3] = {0.f, 0.f, 0.f};
        float ac = 0.f;
#pragma unroll
        for (int kk = 0; kk < 16; kk++) {
            int k = kg * 16 + kk;
            float w = W1[(p * 128 + k) * 128 + j];
#pragma unroll
            for (int i = 0; i < 16; i++) ax[i] += swa[i * 128 + k] * w;
#pragma unroll
            for (int i = 0; i < 3; i++) ap[i] += swp[i * 128 + k] * w;
            ac += sb[k] * w;
        }
#pragma unroll
        for (int i = 0; i < 16; i++) red[(kg * 20 + i) * 128 + j] = ax[i];
#pragma unroll
        for (int i = 0; i < 3; i++) red[(kg * 20 + 16 + i) * 128 + j] = ap[i];
        red[(kg * 20 + 19) * 128 + j] = ac;
        __syncthreads();
        for (int idx = tid; idx < 20 * 128; idx += 1024) {
            int r = idx >> 7, jj = idx & 127;
            float s = 0.f;
#pragma unroll
            for (int kk = 0; kk < 8; kk++) s += red[(kk * 20 + r) * 128 + jj];
            if (r < 16)      g_wx[p][r * 128 + jj] = s;
            else if (r < 19) g_wp[p][(r - 16) * 128 + jj] = s;
            else             g_cb[p][jj] = s;
        }
    } else {
        int c = blockIdx.x - 2;    // k32 chunk
        __half* dst = g_w2h + c * 4096;
        for (int idx = threadIdx.x; idx < 4096; idx += 1024) {
            int u = idx & 3;
            int s = (idx >> 2) & 1;
            int t = (idx >> 3) & 3;
            int n = idx >> 5;
            int kl = s * 16 + ((u >> 1) << 3) + 2 * t + (u & 1);
            dst[idx] = __float2half(W2[(c * 32 + kl) * 128 + n]);
        }
    }
}

// ------------- Kernel 2: per-node h_src / h_tgt (128 thr, unrolled) ---------
__global__ void node_h_kernel(const float* __restrict__ x,
                              const float* __restrict__ pos, int N) {
    int j = threadIdx.x;
    float wx0[16], wx1[16], wp0[3], wp1[3];
#pragma unroll
    for (int i = 0; i < 16; i++) {
        wx0[i] = g_wx[0][i * 128 + j];
        wx1[i] = g_wx[1][i * 128 + j];
    }
#pragma unroll
    for (int i = 0; i < 3; i++) {
        wp0[i] = g_wp[0][i * 128 + j];
        wp1[i] = g_wp[1][i * 128 + j];
    }
    float c0 = g_cb[0][j], c1 = g_cb[1][j];

    __shared__ float xs[NPB][16];
    __shared__ float ps[NPB][3];
    int n0 = blockIdx.x * NPB;
    for (int i = j; i < NPB * 16; i += 128) {
        int n = n0 + (i >> 4);
        xs[i >> 4][i & 15] = (n < N) ? x[n * 16 + (i & 15)] : 0.0f;
    }
    for (int i = j; i < NPB * 3; i += 128) {
        int n = n0 + i / 3;
        ps[i / 3][i % 3] = (n < N) ? pos[n * 3 + i % 3] : 0.0f;
    }
    __syncthreads();
#pragma unroll 4
    for (int n = 0; n < NPB; n++) {
        float s0 = c0, s1 = c1;
#pragma unroll
        for (int i = 0; i < 16; i++) {
            s0 += xs[n][i] * wx0[i];
            s1 += xs[n][i] * wx1[i];
        }
#pragma unroll
        for (int i = 0; i < 3; i++) {
            s0 += ps[n][i] * wp0[i];
            s1 += ps[n][i] * wp1[i];
        }
        if (n0 + n < N) {
            g_hsrc[(n0 + n) * HID + j] = __float2half(s0);
            g_htgt[(n0 + n) * HID + j] = __float2half(s1);
        }
    }
}

// ------------- Kernel 3: edge MLP (batched conv loads) ----------------------
__global__ void __launch_bounds__(THREADS, 2)
edge_mlp10(const float* __restrict__ pos, const int* __restrict__ ei,
           const float* __restrict__ W1, const float* __restrict__ b1,
           const float* __restrict__ b2,
           const float* __restrict__ W3, const float* __restrict__ b3,
           float* __restrict__ out, int E) {
    __shared__ __align__(16) __half hs[BM * HID];        // 32 KB, swizzled
    __shared__ __align__(16) float part[4 * BM * 4];     // 8 KB
    __shared__ int   soff[BM], doff[BM];
    __shared__ __half2 dist2[BM];
    __shared__ __half2 w256h[64], sb1h[64];
    __shared__ float sb2[128], w3s[512], b3s[4];

    const uint32_t hsu = (uint32_t)__cvta_generic_to_shared(hs);
    const int tid  = threadIdx.x;
    const int lane = tid & 31;
    const int wid  = tid >> 5;               // 0..15
    const int m_base = (wid & 3) * 32;       // 4 m-groups of 32 rows
    const int n_warp = (wid >> 2) * 32;      // 4 n-groups of 32 cols
    const int g = lane >> 2;
    const int t = lane & 3;
    const int tile0 = blockIdx.x * BM;

    // ---- setup ----
    w3s[tid] = W3[tid];
    if (tid < BM) {
        int ge = tile0 + tid; if (ge >= E) ge = E - 1;
        int s = ei[ge], d = ei[E + ge];
        soff[tid] = s * HID;
        doff[tid] = d * HID;
        float dx = pos[s * 3 + 0] - pos[d * 3 + 0];
        float dy = pos[s * 3 + 1] - pos[d * 3 + 1];
        float dz = pos[s * 3 + 2] - pos[d * 3 + 2];
        dist2[tid] = __float2half2_rn(sqrtf(dx * dx + dy * dy + dz * dz));
    } else if (tid < 192) {
        int c = tid - 128;
        w256h[c] = __floats2half2_rn(W1[256 * 128 + 2 * c],
                                     W1[256 * 128 + 2 * c + 1]);
        sb1h[c]  = __floats2half2_rn(b1[2 * c], b1[2 * c + 1]);
    } else if (tid < 320) {
        sb2[tid - 192] = b2[tid - 192];
    }
    if (tid < 4) b3s[tid] = b3[tid];
    __syncthreads();

    // ---- conv: coalesced gather (batched 2-pair loads), fp16 silu -> hs ----
    {
        const int g2 = lane >> 3;
        const int sub = lane & 7;
        const int rbase = wid * 8;
#pragma unroll
        for (int pair = 0; pair < 2; pair++) {
            // batch loads for both halves of this row-quad pair (MLP = 4)
            int row0 = rbase + pair * 4 + g2;
            uint4 av0 = *(const uint4*)(g_hsrc + soff[row0] + sub * 8);
            uint4 bv0 = *(const uint4*)(g_htgt + doff[row0] + sub * 8);
            uint4 av1 = *(const uint4*)(g_hsrc + soff[row0] + 64 + sub * 8);
            uint4 bv1 = *(const uint4*)(g_htgt + doff[row0] + 64 + sub * 8);
            __half2 dd2 = dist2[row0];
#pragma unroll
            for (int half = 0; half < 2; half++) {
                const uint4& av = half ? av1 : av0;
                const uint4& bv = half ? bv1 : bv0;
                int cc = half * 8 + sub;
                int h2b = cc * 4;
                const __half2* ah = (const __half2*)&av;
                const __half2* bh = (const __half2*)&bv;
                uint4 ov;
                __half2* oh = (__half2*)&ov;
#pragma unroll
                for (int jj = 0; jj < 4; jj++) {
                    __half2 z = __hfma2(dd2, w256h[h2b + jj],
                                        __hadd2(__hadd2(ah[jj], bh[jj]),
                                                sb1h[h2b + jj]));
                    oh[jj] = h2_silu(z);
                }
                *(uint4*)((char*)hs + row0 * 256 + (sw_pos(row0, cc) << 4)) = ov;
            }
        }
    }
    __syncthreads();

    // ---- GEMM2: h1 @ W2 (K=128), warp tile 32x32, packed B frags -----------
    float4 acc[2][4];
#pragma unroll
    for (int i = 0; i < 2; i++)
#pragma unroll
        for (int j = 0; j < 4; j++) acc[i][j] = make_float4(0.f, 0.f, 0.f, 0.f);
#pragma unroll
    for (int c = 0; c < 4; c++) {
        const __half* Bp = g_w2h + c * 4096;
        uint4 bf[4];
#pragma unroll
        for (int ni = 0; ni < 4; ni++) {
            int n = n_warp + ni * 8 + g;
            bf[ni] = *(const uint4*)(Bp + (n * 4 + t) * 8);
        }
#pragma unroll
        for (int s = 0; s < 2; s++) {
            int sg = c * 2 + s;
#pragma unroll
            for (int mi = 0; mi < 2; mi++) {
                int lrow = m_base + mi * 16 + (lane & 7) + (lane & 8);
                int cc = sg * 2 + (lane >> 4);
                uint32_t addr = hsu + lrow * 256 + (sw_pos(lrow, cc) << 4);
                uint32_t a0, a1, a2, a3;
                ldm4(a0, a1, a2, a3, addr);
#pragma unroll
                for (int ni = 0; ni < 4; ni++) {
                    uint32_t b0 = s ? bf[ni].z : bf[ni].x;
                    uint32_t b1v = s ? bf[ni].w : bf[ni].y;
                    mma16(acc[mi][ni], a0, a1, a2, a3, b0, b1v);
                }
            }
        }
    }

    // ---- epilogue: fp16x2 silu(D2+b2), GEMM3 dot (hoisted w3), shfl --------
    {
        float4 plo[2] = {make_float4(0.f, 0.f, 0.f, 0.f),
                         make_float4(0.f, 0.f, 0.f, 0.f)};
        float4 phi[2] = {make_float4(0.f, 0.f, 0.f, 0.f),
                         make_float4(0.f, 0.f, 0.f, 0.f)};
#pragma unroll
        for (int ni = 0; ni < 4; ni++) {
            int c0 = n_warp + ni * 8 + 2 * t;
            float2 bb = *(const float2*)&sb2[c0];
            float4 w0 = *(const float4*)&w3s[c0 * 4];
            float4 w1 = *(const float4*)&w3s[(c0 + 1) * 4];
#pragma unroll
            for (int mi = 0; mi < 2; mi++) {
                float4 a = acc[mi][ni];
                __half2 zlo = __floats2half2_rn(a.x + bb.x, a.y + bb.y);
                __half2 zhi = __floats2half2_rn(a.z + bb.x, a.w + bb.y);
                float2 vlo = __half22float2(h2_silu(zlo));
                float2 vhi = __half22float2(h2_silu(zhi));
                plo[mi].x += vlo.x * w0.x + vlo.y * w1.x;
                plo[mi].y += vlo.x * w0.y + vlo.y * w1.y;
                plo[mi].z += vlo.x * w0.z + vlo.y * w1.z;
                plo[mi].w += vlo.x * w0.w + vlo.y * w1.w;
                phi[mi].x += vhi.x * w0.x + vhi.y * w1.x;
                phi[mi].y += vhi.x * w0.y + vhi.y * w1.y;
                phi[mi].z += vhi.x * w0.z + vhi.y * w1.z;
                phi[mi].w += vhi.x * w0.w + vhi.y * w1.w;
            }
        }
#pragma unroll
        for (int mi = 0; mi < 2; mi++) {
#pragma unroll
            for (int m = 1; m <= 2; m <<= 1) {
                plo[mi].x += __shfl_xor_sync(0xffffffffu, plo[mi].x, m);
                plo[mi].y += __shfl_xor_sync(0xffffffffu, plo[mi].y, m);
                plo[mi].z += __shfl_xor_sync(0xffffffffu, plo[mi].z, m);
                plo[mi].w += __shfl_xor_sync(0xffffffffu, plo[mi].w, m);
                phi[mi].x += __shfl_xor_sync(0xffffffffu, phi[mi].x, m);
                phi[mi].y += __shfl_xor_sync(0xffffffffu, phi[mi].y, m);
                phi[mi].z += __shfl_xor_sync(0xffffffffu, phi[mi].z, m);
                phi[mi].w += __shfl_xor_sync(0xffffffffu, phi[mi].w, m);
            }
            if (t == 0) {
                int r = m_base + mi * 16 + g;
                int ng = wid >> 2;
                *(float4*)&part[(ng * BM + r) * 4] = plo[mi];
                *(float4*)&part[(ng * BM + r + 8) * 4] = phi[mi];
            }
        }
    }
    __syncthreads();

    if (tid < BM) {
        int ge = tile0 + tid;
        float4 o = make_float4(b3s[0], b3s[1], b3s[2], b3s[3]);
#pragma unroll
        for (int ng = 0; ng < 4; ng++) {
            float4 pv = *(const float4*)&part[(ng * BM + tid) * 4];
            o.x += pv.x; o.y += pv.y; o.z += pv.z; o.w += pv.w;
        }
        if (ge < E) *(float4*)&out[ge * 4] = o;
    }
}

// ---------------------------------------------------------------------------
extern "C" void kernel_launch(void* const* d_in, const int* in_sizes, int n_in,
                              void* d_out, int out_size) {
    const float* x   = (const float*)d_in[0];
    const float* pos = (const float*)d_in[1];
    const int*   ei  = (const int*)  d_in[2];
    const float* Wa  = (const float*)d_in[3];
    const float* ba  = (const float*)d_in[4];
    const float* Wp  = (const float*)d_in[5];
    const float* bp  = (const float*)d_in[6];
    const float* W1  = (const float*)d_in[7];
    const float* b1  = (const float*)d_in[8];
    const float* W2  = (const float*)d_in[9];
    const float* b2  = (const float*)d_in[10];
    const float* W3  = (const float*)d_in[11];
    const float* b3  = (const float*)d_in[12];
    float* out = (float*)d_out;

    int N = in_sizes[0] / 16;
    int E = in_sizes[2] / 2;

    size_t prep_smem = 8 * 20 * 128 * sizeof(float);   // 80 KB
    cudaFuncSetAttribute(prep_all,
                         cudaFuncAttributeMaxDynamicSharedMemorySize,
                         (int)prep_smem);

    prep_all<<<6, 1024, prep_smem>>>(Wa, ba, Wp, bp, W1, W2);
    node_h_kernel<<<(N + NPB - 1) / NPB, 128>>>(x, pos, N);
    edge_mlp10<<<(E + BM - 1) / BM, THREADS>>>(
        pos, ei, W1, b1, b2, W3, b3, out, E);
}